// round 9
// baseline (speedup 1.0000x reference)
#include <cuda_runtime.h>
#include <cuda_bf16.h>
#include <cstdint>

// RochetNet forward — HMMA (mma.sync bf16) phase A + exact-order rescue phase B.
// (tcgen05 is unavailable: this toolchain assembles .target sm_103, which
//  rejects tcgen05/.cta_group. mma.sync.m16n8k16 bf16 is sm_80+ and works.)
//
// Phase A: per-CTA 128 rows (8 warps x m16). hidden = bf16 HMMA(V, W^T) fp32
//   accum + w0. Rows with top-2 gap > GAP_THR and |max| > SGN_THR finalize:
//     alloc = clip(W[idx]) from fp32 W (global, L2-resident),
//     pay   = relu(-w0[idx]) if max>0   (identity: sum(alloc*v)=hidden-w0[idx]
//                                        since clip(W)=W for W in [0,1)).
//   Near-ties / near-zero max rows go to the tie queue.
// Phase B: exact serial-order fp32 rescore (reference rounding order), proven
//   in round 2 (rel_err 1.66e-5).
//
// Output: alloc [B*64] floats, then payments [B].

#define ITEMS   64
#define HIDDEN  256
#define TILE_M  128
#define BMAX    1000000
#define GAP_THR 0.04f
#define SGN_THR 0.02f

__device__ int g_tie_count;
__device__ int g_tie_rows[BMAX];

__global__ void zero_count_kernel() { g_tie_count = 0; }

// ---------------------------------------------------------------- helpers ---
__device__ __forceinline__ uint32_t smem_u32(const void* p) {
    uint32_t a;
    asm("{ .reg .u64 t; cvta.to.shared.u64 t, %1; cvt.u32.u64 %0, t; }"
        : "=r"(a) : "l"(p));
    return a;
}
// res = packed bf16x2 {lo=a, hi=b}
#define CVT_BF16X2_F32(res, a, b) \
    asm("cvt.rn.satfinite.bf16x2.f32 %0, %1, %2;" : "=r"(res) : "f"(b), "f"(a))

#define LDSM_X4(r0, r1, r2, r3, addr) \
    asm volatile("ldmatrix.sync.aligned.m8n8.x4.shared.b16 {%0,%1,%2,%3}, [%4];" \
                 : "=r"(r0), "=r"(r1), "=r"(r2), "=r"(r3) : "r"(addr))

#define MMA_16816(d0, d1, d2, d3, a0, a1, a2, a3, b0, b1) \
    asm volatile("mma.sync.aligned.m16n8k16.row.col.f32.bf16.bf16.f32 " \
                 "{%0,%1,%2,%3}, {%4,%5,%6,%7}, {%8,%9}, {%0,%1,%2,%3};" \
                 : "+f"(d0), "+f"(d1), "+f"(d2), "+f"(d3) \
                 : "r"(a0), "r"(a1), "r"(a2), "r"(a3), "r"(b0), "r"(b1))

// ---------------------------------------------------------------- smem ------
// W bf16: 256 rows x 72 bf16 (144 B, 16 B pad -> conflict-free ldmatrix)
// V bf16: 8 warps x 16 rows x 72 bf16
// w0: 256 f32; stage: per warp 16 x {enc, pay}
#define WROW_B    144
#define SM_WB     0
#define SM_VB     (SM_WB + HIDDEN * WROW_B)            // 36864
#define SM_W0     (SM_VB + 8 * 16 * WROW_B)            // 55296
#define SM_SIDX   (SM_W0 + HIDDEN * 4)                 // 56320
#define SM_SPAY   (SM_SIDX + 8 * 16 * 4)               // 56832
#define SM_TOTAL  (SM_SPAY + 8 * 16 * 4)               // 57344

// ---------------------------------------------------------------- Phase A ---
__global__ void __launch_bounds__(256, 2)
rochet_hmma_kernel(const float* __restrict__ V,
                   const float* __restrict__ W,
                   const float* __restrict__ w0,
                   float* __restrict__ alloc_out,
                   float* __restrict__ pay_out,
                   int B) {
    extern __shared__ char smem[];
    const int tid  = threadIdx.x;
    const int wid  = tid >> 5;
    const int lane = tid & 31;

    float* w0s = (float*)(smem + SM_W0);
    int*   sIdx = (int*)(smem + SM_SIDX);
    float* sPay = (float*)(smem + SM_SPAY);

    // ---- Load W -> bf16 padded smem, and w0.
    for (int i = tid; i < HIDDEN * ITEMS / 4; i += 256) {   // 4096 float4
        float4 f = __ldg((const float4*)W + i);
        int row = i >> 4, c4 = i & 15;
        uint32_t b0, b1;
        CVT_BF16X2_F32(b0, f.x, f.y);
        CVT_BF16X2_F32(b1, f.z, f.w);
        *(uint2*)(smem + SM_WB + row * WROW_B + c4 * 8) = make_uint2(b0, b1);
    }
    if (tid < HIDDEN) w0s[tid] = __ldg(w0 + tid);
    __syncthreads();

    const int base = blockIdx.x * TILE_M + wid * 16;    // warp's first row

    // ---- Load warp's V slab (16 x 64 f32 -> bf16 padded smem).
    char* vb = smem + SM_VB + wid * 16 * WROW_B;
    #pragma unroll
    for (int it = 0; it < 8; it++) {
        int idx = it * 32 + lane;        // 256 float4 slots
        int row = idx >> 4, c4 = idx & 15;
        int grow = base + row;
        float4 f = (grow < B)
            ? __ldg((const float4*)(V + (size_t)grow * ITEMS) + c4)
            : make_float4(0.f, 0.f, 0.f, 0.f);
        uint32_t b0, b1;
        CVT_BF16X2_F32(b0, f.x, f.y);
        CVT_BF16X2_F32(b1, f.z, f.w);
        *(uint2*)(vb + row * WROW_B + c4 * 8) = make_uint2(b0, b1);
    }
    __syncwarp();

    // ---- A fragments (m16 x k64), loaded once.
    uint32_t a[4][4];
    {
        const uint32_t arow = lane & 15;
        const uint32_t acol = (lane & 16) >> 1;          // 0 or 8
        uint32_t abase = smem_u32(vb) + arow * WROW_B + acol * 2;
        #pragma unroll
        for (int kk = 0; kk < 4; kk++)
            LDSM_X4(a[kk][0], a[kk][1], a[kk][2], a[kk][3],
                    abase + kk * 32);                    // 16 bf16 = 32 B
    }

    // ---- Scan 256 hidden units, 8 at a time.
    float best0 = -1e30f, sec0 = -1e30f, best1 = -1e30f, sec1 = -1e30f;
    int   idx0 = 0, idx1 = 0;
    const uint32_t brow  = lane & 7;
    const uint32_t bcol8 = ((lane >> 3) & 3) * 8;
    const uint32_t wbase = smem_u32(smem + SM_WB) + brow * WROW_B + bcol8 * 2;
    const int      cbase = 2 * (lane & 3);

    #pragma unroll 4
    for (int nt = 0; nt < 32; nt++) {
        uint32_t b[8];
        uint32_t ad = wbase + (uint32_t)nt * 8 * WROW_B;
        LDSM_X4(b[0], b[1], b[2], b[3], ad);             // k 0..31
        LDSM_X4(b[4], b[5], b[6], b[7], ad + 64);        // k 32..63
        float d0 = 0.f, d1 = 0.f, d2 = 0.f, d3 = 0.f;
        MMA_16816(d0, d1, d2, d3, a[0][0], a[0][1], a[0][2], a[0][3], b[0], b[1]);
        MMA_16816(d0, d1, d2, d3, a[1][0], a[1][1], a[1][2], a[1][3], b[2], b[3]);
        MMA_16816(d0, d1, d2, d3, a[2][0], a[2][1], a[2][2], a[2][3], b[4], b[5]);
        MMA_16816(d0, d1, d2, d3, a[3][0], a[3][1], a[3][2], a[3][3], b[6], b[7]);

        const int  col = nt * 8 + cbase;
        float2 wv = *(const float2*)(w0s + col);
        float h;
        h = d0 + wv.x;
        if (h > best0) { sec0 = best0; best0 = h; idx0 = col; }
        else if (h > sec0) sec0 = h;
        h = d1 + wv.y;
        if (h > best0) { sec0 = best0; best0 = h; idx0 = col + 1; }
        else if (h > sec0) sec0 = h;
        h = d2 + wv.x;
        if (h > best1) { sec1 = best1; best1 = h; idx1 = col; }
        else if (h > sec1) sec1 = h;
        h = d3 + wv.y;
        if (h > best1) { sec1 = best1; best1 = h; idx1 = col + 1; }
        else if (h > sec1) sec1 = h;
    }

    // ---- Merge across the 4 lanes of each quad (they share rows).
    #pragma unroll
    for (int off = 1; off <= 2; off <<= 1) {
        float ob, os; int oi;
        ob = __shfl_xor_sync(0xffffffffu, best0, off);
        os = __shfl_xor_sync(0xffffffffu, sec0,  off);
        oi = __shfl_xor_sync(0xffffffffu, idx0,  off);
        sec0 = fmaxf(fmaxf(sec0, os), fminf(best0, ob));
        if (ob > best0 || (ob == best0 && oi < idx0)) { best0 = ob; idx0 = oi; }
        ob = __shfl_xor_sync(0xffffffffu, best1, off);
        os = __shfl_xor_sync(0xffffffffu, sec1,  off);
        oi = __shfl_xor_sync(0xffffffffu, idx1,  off);
        sec1 = fmaxf(fmaxf(sec1, os), fminf(best1, ob));
        if (ob > best1 || (ob == best1 && oi < idx1)) { best1 = ob; idx1 = oi; }
    }

    // ---- Stage per-row decisions (lane 0 of each quad owns rows q, q+8).
    if ((lane & 3) == 0) {
        const int q = lane >> 2;
        #pragma unroll
        for (int half = 0; half < 2; half++) {
            const int   r    = q + half * 8;
            const float b    = half ? best1 : best0;
            const float s    = half ? sec1  : sec0;
            const int   bi   = half ? idx1  : idx0;
            const int   grow = base + r;
            int enc = -1;
            float pay = 0.f;
            if (grow < B) {
                if ((b - s <= GAP_THR) || (fabsf(b) <= SGN_THR)) {
                    int slot = atomicAdd(&g_tie_count, 1);
                    g_tie_rows[slot] = grow;
                } else {
                    const int win = (b > 0.f) ? 1 : 0;
                    enc = bi | (win << 16);
                    pay = win ? fmaxf(-w0s[bi], 0.f) : 0.f;
                }
            }
            sIdx[wid * 16 + r] = enc;
            sPay[wid * 16 + r] = pay;
        }
    }
    __syncwarp();

    // ---- Warp-cooperative alloc writes (coalesced 256 B rows).
    #pragma unroll 1
    for (int r = 0; r < 16; r++) {
        const int enc = sIdx[wid * 16 + r];
        if (enc < 0) continue;
        const int grow = base + r;
        const int win  = enc >> 16;
        const int bi   = enc & 0xffff;
        float2 t = make_float2(0.f, 0.f);
        if (win) {
            t = __ldg((const float2*)(W + (size_t)bi * ITEMS) + lane);
            t.x = fminf(fmaxf(t.x, 0.f), 1.f);
            t.y = fminf(fmaxf(t.y, 0.f), 1.f);
        }
        ((float2*)(alloc_out + (size_t)grow * ITEMS))[lane] = t;
        if (lane == 0) pay_out[grow] = sPay[wid * 16 + r];
    }
}

// ---------------------------------------------------------------- Phase B ---
// One warp per queued row; exact serial-order fp32 scoring (reference order).
__global__ __launch_bounds__(256)
void rochet_phaseB_kernel(const float* __restrict__ V,
                          const float* __restrict__ W,
                          const float* __restrict__ w0,
                          float* __restrict__ alloc_out,
                          float* __restrict__ pay_out) {
    const int lane        = threadIdx.x & 31;
    const int warp_global = (blockIdx.x * blockDim.x + threadIdx.x) >> 5;
    const int nwarps      = (gridDim.x * blockDim.x) >> 5;
    const int cnt         = g_tie_count;

    for (int q = warp_global; q < cnt; q += nwarps) {
        const int row = g_tie_rows[q];
        const float* v = V + (size_t)row * ITEMS;

        float vr[ITEMS];
        #pragma unroll
        for (int i = 0; i < ITEMS / 4; i++) {
            float4 t = reinterpret_cast<const float4*>(v)[i];
            vr[4 * i + 0] = t.x; vr[4 * i + 1] = t.y;
            vr[4 * i + 2] = t.z; vr[4 * i + 3] = t.w;
        }

        float best = -1e30f;
        int   bidx = HIDDEN;
        #pragma unroll 1
        for (int jj = 0; jj < HIDDEN / 32; jj++) {
            const int j = lane * (HIDDEN / 32) + jj;
            const float* wr = W + j * ITEMS;
            float acc = 0.0f;
            #pragma unroll
            for (int i = 0; i < ITEMS; i++)
                acc = fmaf(vr[i], __ldg(wr + i), acc);   // strict serial order
            float h = acc + __ldg(w0 + j);               // single bias rounding
            if (h > best || (h == best && j < bidx)) { best = h; bidx = j; }
        }
        #pragma unroll
        for (int off = 16; off; off >>= 1) {
            float ov = __shfl_down_sync(0xffffffffu, best, off);
            int   oi = __shfl_down_sync(0xffffffffu, bidx, off);
            if (ov > best || (ov == best && oi < bidx)) { best = ov; bidx = oi; }
        }
        best = __shfl_sync(0xffffffffu, best, 0);
        bidx = __shfl_sync(0xffffffffu, bidx, 0);

        const bool win = (best > 0.0f);
        float w_0 = __ldg(W + bidx * ITEMS + 2 * lane + 0);
        float w_1 = __ldg(W + bidx * ITEMS + 2 * lane + 1);
        w_0 = fminf(fmaxf(w_0, 0.0f), 1.0f);
        w_1 = fminf(fmaxf(w_1, 0.0f), 1.0f);
        if (!win) { w_0 = 0.0f; w_1 = 0.0f; }
        alloc_out[(size_t)row * ITEMS + 2 * lane + 0] = w_0;
        alloc_out[(size_t)row * ITEMS + 2 * lane + 1] = w_1;

        float pd = fmaf(w_1, vr[2 * lane + 1], w_0 * vr[2 * lane]);
        #pragma unroll
        for (int off = 16; off; off >>= 1)
            pd += __shfl_down_sync(0xffffffffu, pd, off);
        if (lane == 0)
            pay_out[row] = fmaxf(pd - fmaxf(best, 0.0f), 0.0f);
    }
}

extern "C" void kernel_launch(void* const* d_in, const int* in_sizes, int n_in,
                              void* d_out, int out_size) {
    const float* V  = (const float*)d_in[0];   // [B, 64]
    const float* W  = (const float*)d_in[1];   // [256, 64]
    const float* w0 = (const float*)d_in[2];   // [256]

    const int B = in_sizes[0] / ITEMS;
    float* alloc_out = (float*)d_out;
    float* pay_out   = (float*)d_out + (size_t)B * ITEMS;

    const int ntiles = (B + TILE_M - 1) / TILE_M;

    // One-time setup (kept out of the graph-captured call sequence).
    static bool inited = false;
    if (!inited) {
        inited = true;
        cudaFuncSetAttribute(rochet_hmma_kernel,
                             cudaFuncAttributeMaxDynamicSharedMemorySize,
                             SM_TOTAL);
    }

    zero_count_kernel<<<1, 1>>>();
    rochet_hmma_kernel<<<ntiles, 256, SM_TOTAL>>>(V, W, w0, alloc_out,
                                                  pay_out, B);
    rochet_phaseB_kernel<<<1024, 256>>>(V, W, w0, alloc_out, pay_out);
}

// round 11
// speedup vs baseline: 13.2110x; 13.2110x over previous
#include <cuda_runtime.h>
#include <cuda_bf16.h>
#include <cstdint>

// RochetNet forward — split-bf16 HMMA phase A (fp32-grade accuracy) +
// smem-staged exact-order rescue phase B.
//
// Phase A: hidden = (vh+vl)·(Wh+Wl)^T + w0 via 3 bf16 MMA passes
//   (vh·Wh + vl·Wh + vh·Wl), worst-case |err| ~7e-4. Rows with top-2 gap
//   > GAP_THR(3e-3) and |max| > SGN_THR finalize directly:
//     alloc = clip(W[idx]) (fp32), pay = relu(-w0[idx]) if max>0
//     (identity: sum(alloc*v) = hidden[idx]-w0[idx] since clip(W)=W).
//   Near-ties go to the tie queue (~0.5% expected).
// Phase B: exact serial-order fp32 rescore from SMEM-staged W (conflict-free
//   padded layout), matching reference rounding order.
//
// Output: alloc [B*64] floats, then payments [B].

#define ITEMS   64
#define HIDDEN  256
#define TILE_M  128
#define BMAX    1000000
#define GAP_THR 3e-3f
#define SGN_THR 2e-3f

__device__ int g_tie_count;
__device__ int g_tie_rows[BMAX];

__global__ void zero_count_kernel() { g_tie_count = 0; }

// ---------------------------------------------------------------- helpers ---
__device__ __forceinline__ uint32_t smem_u32(const void* p) {
    uint32_t a;
    asm("{ .reg .u64 t; cvta.to.shared.u64 t, %1; cvt.u32.u64 %0, t; }"
        : "=r"(a) : "l"(p));
    return a;
}
// res = packed bf16x2 {lo=a, hi=b}
#define CVT_BF16X2_F32(res, a, b) \
    asm("cvt.rn.satfinite.bf16x2.f32 %0, %1, %2;" : "=r"(res) : "f"(b), "f"(a))

#define LDSM_X4(r0, r1, r2, r3, addr) \
    asm volatile("ldmatrix.sync.aligned.m8n8.x4.shared.b16 {%0,%1,%2,%3}, [%4];" \
                 : "=r"(r0), "=r"(r1), "=r"(r2), "=r"(r3) : "r"(addr))

#define MMA_16816(d0, d1, d2, d3, a0, a1, a2, a3, b0, b1) \
    asm volatile("mma.sync.aligned.m16n8k16.row.col.f32.bf16.bf16.f32 " \
                 "{%0,%1,%2,%3}, {%4,%5,%6,%7}, {%8,%9}, {%0,%1,%2,%3};" \
                 : "+f"(d0), "+f"(d1), "+f"(d2), "+f"(d3) \
                 : "r"(a0), "r"(a1), "r"(a2), "r"(a3), "r"(b0), "r"(b1))

// ---------------------------------------------------------------- smem (A) --
// Wh/Wl bf16: 256 rows x 72 bf16 (144 B, padded -> conflict-free ldmatrix)
// Vh/Vl bf16: 8 warps x 16 rows x 144 B each
#define WROW_B   144
#define SM_WH    0
#define SM_WL    (SM_WH + HIDDEN * WROW_B)            // 36864
#define SM_VH    (SM_WL + HIDDEN * WROW_B)            // 73728
#define SM_VL    (SM_VH + 8 * 16 * WROW_B)            // 92160
#define SM_W0    (SM_VL + 8 * 16 * WROW_B)            // 110592
#define SM_SIDX  (SM_W0 + HIDDEN * 4)                 // 111616
#define SM_SPAY  (SM_SIDX + 8 * 16 * 4)               // 112128
#define SM_TOTAL (SM_SPAY + 8 * 16 * 4)               // 112640

// split f32 -> (hi bf16x2, lo bf16x2) for a float pair
__device__ __forceinline__ void split2(float x, float y,
                                       uint32_t& hi, uint32_t& lo) {
    CVT_BF16X2_F32(hi, x, y);
    float hx = __uint_as_float(hi << 16);
    float hy = __uint_as_float(hi & 0xffff0000u);
    CVT_BF16X2_F32(lo, x - hx, y - hy);   // exact residual (bit-aligned sub)
}

// ---------------------------------------------------------------- Phase A ---
__global__ void __launch_bounds__(256, 2)
rochet_hmma_kernel(const float* __restrict__ V,
                   const float* __restrict__ W,
                   const float* __restrict__ w0,
                   float* __restrict__ alloc_out,
                   float* __restrict__ pay_out,
                   int B) {
    extern __shared__ char smem[];
    const int tid  = threadIdx.x;
    const int wid  = tid >> 5;
    const int lane = tid & 31;

    float* w0s  = (float*)(smem + SM_W0);
    int*   sIdx = (int*)(smem + SM_SIDX);
    float* sPay = (float*)(smem + SM_SPAY);

    // ---- Load W -> split bf16 (hi/lo) padded smem, and w0.
    for (int i = tid; i < HIDDEN * ITEMS / 4; i += 256) {   // 4096 float4
        float4 f = __ldg((const float4*)W + i);
        int row = i >> 4, c4 = i & 15;
        uint32_t h0, l0, h1, l1;
        split2(f.x, f.y, h0, l0);
        split2(f.z, f.w, h1, l1);
        *(uint2*)(smem + SM_WH + row * WROW_B + c4 * 8) = make_uint2(h0, h1);
        *(uint2*)(smem + SM_WL + row * WROW_B + c4 * 8) = make_uint2(l0, l1);
    }
    if (tid < HIDDEN) w0s[tid] = __ldg(w0 + tid);
    __syncthreads();

    const int base = blockIdx.x * TILE_M + wid * 16;    // warp's first row

    // ---- Load warp's V slab, split into hi/lo bf16.
    char* vh = smem + SM_VH + wid * 16 * WROW_B;
    char* vl = smem + SM_VL + wid * 16 * WROW_B;
    #pragma unroll
    for (int it = 0; it < 8; it++) {
        int idx = it * 32 + lane;        // 256 float4 slots
        int row = idx >> 4, c4 = idx & 15;
        int grow = base + row;
        float4 f = (grow < B)
            ? __ldg((const float4*)(V + (size_t)grow * ITEMS) + c4)
            : make_float4(0.f, 0.f, 0.f, 0.f);
        uint32_t h0, l0, h1, l1;
        split2(f.x, f.y, h0, l0);
        split2(f.z, f.w, h1, l1);
        *(uint2*)(vh + row * WROW_B + c4 * 8) = make_uint2(h0, h1);
        *(uint2*)(vl + row * WROW_B + c4 * 8) = make_uint2(l0, l1);
    }
    __syncwarp();

    // ---- A fragments (m16 x k64) hi and lo, loaded once.
    uint32_t ah[4][4], al[4][4];
    {
        const uint32_t arow = lane & 15;
        const uint32_t acol = (lane & 16) >> 1;          // 0 or 8
        uint32_t hb = smem_u32(vh) + arow * WROW_B + acol * 2;
        uint32_t lb = smem_u32(vl) + arow * WROW_B + acol * 2;
        #pragma unroll
        for (int kk = 0; kk < 4; kk++) {
            LDSM_X4(ah[kk][0], ah[kk][1], ah[kk][2], ah[kk][3], hb + kk * 32);
            LDSM_X4(al[kk][0], al[kk][1], al[kk][2], al[kk][3], lb + kk * 32);
        }
    }

    // ---- Scan 256 hidden units, 8 at a time; 3 MMA passes per k-step.
    float best0 = -1e30f, sec0 = -1e30f, best1 = -1e30f, sec1 = -1e30f;
    int   idx0 = 0, idx1 = 0;
    const uint32_t brow  = lane & 7;
    const uint32_t bcol8 = ((lane >> 3) & 3) * 8;
    const uint32_t whb = smem_u32(smem + SM_WH) + brow * WROW_B + bcol8 * 2;
    const uint32_t wlb = smem_u32(smem + SM_WL) + brow * WROW_B + bcol8 * 2;
    const int      cbase = 2 * (lane & 3);

    #pragma unroll 2
    for (int nt = 0; nt < 32; nt++) {
        uint32_t bh[8], bl[8];
        uint32_t adh = whb + (uint32_t)nt * 8 * WROW_B;
        uint32_t adl = wlb + (uint32_t)nt * 8 * WROW_B;
        LDSM_X4(bh[0], bh[1], bh[2], bh[3], adh);        // k 0..31
        LDSM_X4(bh[4], bh[5], bh[6], bh[7], adh + 64);   // k 32..63
        LDSM_X4(bl[0], bl[1], bl[2], bl[3], adl);
        LDSM_X4(bl[4], bl[5], bl[6], bl[7], adl + 64);

        float d0 = 0.f, d1 = 0.f, d2 = 0.f, d3 = 0.f;    // main: vh*Wh
        float e0 = 0.f, e1 = 0.f, e2 = 0.f, e3 = 0.f;    // corr: vl*Wh + vh*Wl
        #pragma unroll
        for (int kk = 0; kk < 4; kk++) {
            MMA_16816(d0, d1, d2, d3,
                      ah[kk][0], ah[kk][1], ah[kk][2], ah[kk][3],
                      bh[2 * kk], bh[2 * kk + 1]);
            MMA_16816(e0, e1, e2, e3,
                      al[kk][0], al[kk][1], al[kk][2], al[kk][3],
                      bh[2 * kk], bh[2 * kk + 1]);
            MMA_16816(e0, e1, e2, e3,
                      ah[kk][0], ah[kk][1], ah[kk][2], ah[kk][3],
                      bl[2 * kk], bl[2 * kk + 1]);
        }

        const int  col = nt * 8 + cbase;
        float2 wv = *(const float2*)(w0s + col);
        float h;
        h = (d0 + e0) + wv.x;
        if (h > best0) { sec0 = best0; best0 = h; idx0 = col; }
        else if (h > sec0) sec0 = h;
        h = (d1 + e1) + wv.y;
        if (h > best0) { sec0 = best0; best0 = h; idx0 = col + 1; }
        else if (h > sec0) sec0 = h;
        h = (d2 + e2) + wv.x;
        if (h > best1) { sec1 = best1; best1 = h; idx1 = col; }
        else if (h > sec1) sec1 = h;
        h = (d3 + e3) + wv.y;
        if (h > best1) { sec1 = best1; best1 = h; idx1 = col + 1; }
        else if (h > sec1) sec1 = h;
    }

    // ---- Merge across the 4 lanes of each quad (they share rows).
    #pragma unroll
    for (int off = 1; off <= 2; off <<= 1) {
        float ob, os; int oi;
        ob = __shfl_xor_sync(0xffffffffu, best0, off);
        os = __shfl_xor_sync(0xffffffffu, sec0,  off);
        oi = __shfl_xor_sync(0xffffffffu, idx0,  off);
        sec0 = fmaxf(fmaxf(sec0, os), fminf(best0, ob));
        if (ob > best0 || (ob == best0 && oi < idx0)) { best0 = ob; idx0 = oi; }
        ob = __shfl_xor_sync(0xffffffffu, best1, off);
        os = __shfl_xor_sync(0xffffffffu, sec1,  off);
        oi = __shfl_xor_sync(0xffffffffu, idx1,  off);
        sec1 = fmaxf(fmaxf(sec1, os), fminf(best1, ob));
        if (ob > best1 || (ob == best1 && oi < idx1)) { best1 = ob; idx1 = oi; }
    }

    // ---- Stage per-row decisions (lane 0 of each quad owns rows q, q+8).
    if ((lane & 3) == 0) {
        const int q = lane >> 2;
        #pragma unroll
        for (int half = 0; half < 2; half++) {
            const int   r    = q + half * 8;
            const float b    = half ? best1 : best0;
            const float s    = half ? sec1  : sec0;
            const int   bi   = half ? idx1  : idx0;
            const int   grow = base + r;
            int enc = -1;
            float pay = 0.f;
            if (grow < B) {
                if ((b - s <= GAP_THR) || (fabsf(b) <= SGN_THR)) {
                    int slot = atomicAdd(&g_tie_count, 1);
                    g_tie_rows[slot] = grow;
                } else {
                    const int win = (b > 0.f) ? 1 : 0;
                    enc = bi | (win << 16);
                    pay = win ? fmaxf(-w0s[bi], 0.f) : 0.f;
                }
            }
            sIdx[wid * 16 + r] = enc;
            sPay[wid * 16 + r] = pay;
        }
    }
    __syncwarp();

    // ---- Warp-cooperative alloc writes (coalesced 256 B rows).
    #pragma unroll 1
    for (int r = 0; r < 16; r++) {
        const int enc = sIdx[wid * 16 + r];
        if (enc < 0) continue;
        const int grow = base + r;
        const int win  = enc >> 16;
        const int bi   = enc & 0xffff;
        float2 t = make_float2(0.f, 0.f);
        if (win) {
            t = __ldg((const float2*)(W + (size_t)bi * ITEMS) + lane);
            t.x = fminf(fmaxf(t.x, 0.f), 1.f);
            t.y = fminf(fmaxf(t.y, 0.f), 1.f);
        }
        ((float2*)(alloc_out + (size_t)grow * ITEMS))[lane] = t;
        if (lane == 0) pay_out[grow] = sPay[wid * 16 + r];
    }
}

// ---------------------------------------------------------------- Phase B ---
// W staged in smem [256][65] f32 (pad 65 -> lane bank (l+i)%32, conflict-free;
// lane l scores units j = jj*32 + l). Exact serial-order fp32 accumulation.
#define BROW 65
#define SMB_TOTAL (HIDDEN * BROW * 4 + HIDDEN * 4)

__global__ void __launch_bounds__(256)
rochet_phaseB_kernel(const float* __restrict__ V,
                     const float* __restrict__ W,
                     const float* __restrict__ w0,
                     float* __restrict__ alloc_out,
                     float* __restrict__ pay_out) {
    extern __shared__ float shb[];
    float* Ws  = shb;                       // [256][65]
    float* w0s = shb + HIDDEN * BROW;

    const int tid  = threadIdx.x;
    const int lane = tid & 31;

    for (int i = tid; i < HIDDEN * ITEMS; i += 256) {
        int row = i >> 6, col = i & 63;
        Ws[row * BROW + col] = __ldg(W + i);
    }
    if (tid < HIDDEN) w0s[tid] = __ldg(w0 + tid);
    __syncthreads();

    const int warp_global = (blockIdx.x * blockDim.x + tid) >> 5;
    const int nwarps      = (gridDim.x * blockDim.x) >> 5;
    const int cnt         = g_tie_count;

    for (int q = warp_global; q < cnt; q += nwarps) {
        const int row = g_tie_rows[q];
        const float* v = V + (size_t)row * ITEMS;

        float vr[ITEMS];
        #pragma unroll
        for (int i = 0; i < ITEMS / 4; i++) {
            float4 t = reinterpret_cast<const float4*>(v)[i];
            vr[4 * i + 0] = t.x; vr[4 * i + 1] = t.y;
            vr[4 * i + 2] = t.z; vr[4 * i + 3] = t.w;
        }

        float best = -1e30f;
        int   bidx = HIDDEN;
        #pragma unroll 1
        for (int jj = 0; jj < HIDDEN / 32; jj++) {
            const int j = jj * 32 + lane;
            const float* wr = Ws + j * BROW;
            float acc = 0.0f;
            #pragma unroll
            for (int i = 0; i < ITEMS; i++)
                acc = fmaf(vr[i], wr[i], acc);           // strict serial order
            float h = acc + w0s[j];                      // single bias rounding
            if (h > best || (h == best && j < bidx)) { best = h; bidx = j; }
        }
        #pragma unroll
        for (int off = 16; off; off >>= 1) {
            float ov = __shfl_down_sync(0xffffffffu, best, off);
            int   oi = __shfl_down_sync(0xffffffffu, bidx, off);
            if (ov > best || (ov == best && oi < bidx)) { best = ov; bidx = oi; }
        }
        best = __shfl_sync(0xffffffffu, best, 0);
        bidx = __shfl_sync(0xffffffffu, bidx, 0);

        const bool win = (best > 0.0f);
        float2 t = make_float2(0.f, 0.f);
        if (win) {
            t = __ldg((const float2*)(W + (size_t)bidx * ITEMS) + lane);
            t.x = fminf(fmaxf(t.x, 0.0f), 1.0f);
            t.y = fminf(fmaxf(t.y, 0.0f), 1.0f);
        }
        ((float2*)(alloc_out + (size_t)row * ITEMS))[lane] = t;

        float pd = fmaf(t.y, vr[2 * lane + 1], t.x * vr[2 * lane]);
        #pragma unroll
        for (int off = 16; off; off >>= 1)
            pd += __shfl_down_sync(0xffffffffu, pd, off);
        if (lane == 0)
            pay_out[row] = fmaxf(pd - fmaxf(best, 0.0f), 0.0f);
    }
}

extern "C" void kernel_launch(void* const* d_in, const int* in_sizes, int n_in,
                              void* d_out, int out_size) {
    const float* V  = (const float*)d_in[0];   // [B, 64]
    const float* W  = (const float*)d_in[1];   // [256, 64]
    const float* w0 = (const float*)d_in[2];   // [256]

    const int B = in_sizes[0] / ITEMS;
    float* alloc_out = (float*)d_out;
    float* pay_out   = (float*)d_out + (size_t)B * ITEMS;

    const int ntiles = (B + TILE_M - 1) / TILE_M;

    // One-time setup (kept out of the graph-captured call sequence).
    static bool inited = false;
    if (!inited) {
        inited = true;
        cudaFuncSetAttribute(rochet_hmma_kernel,
                             cudaFuncAttributeMaxDynamicSharedMemorySize,
                             SM_TOTAL);
        cudaFuncSetAttribute(rochet_phaseB_kernel,
                             cudaFuncAttributeMaxDynamicSharedMemorySize,
                             SMB_TOTAL);
    }

    zero_count_kernel<<<1, 1>>>();
    rochet_hmma_kernel<<<ntiles, 256, SM_TOTAL>>>(V, W, w0, alloc_out,
                                                  pay_out, B);
    rochet_phaseB_kernel<<<296, 256, SMB_TOTAL>>>(V, W, w0, alloc_out,
                                                  pay_out);
}